// round 6
// baseline (speedup 1.0000x reference)
#include <cuda_runtime.h>
#include <cuda_fp16.h>
#include <cstdint>

// ---------------------------------------------------------------------------
// RBF layer: out[b,l] = exp(-gamma * max(||x_b||^2 + ||lm_l||^2 - 2 x_b.lm_l, 0))
// B=8192, L=2048, D=256, gamma = 1/256.
// Legacy tensor path (tcgen05 unavailable at plain sm_103 PTX target):
// mma.sync.m16n8k16.f16 fp32-accum, ldmatrix, 3-stage cp.async K pipeline.
// R6: register double-buffering of A/B fragments across k-steps so LDSM
// latency is hidden behind the 16-MMA issue window of the previous step.
// ---------------------------------------------------------------------------

#define BB 8192
#define LL 2048
#define DD 256
#define TM 128
#define TN 128

// smem: 3 stages x (A 16KB + B 16KB) + l2 tile
#define STAGE_BYTES 32768
#define SMEM_L2     98304
#define SMEM_SIZE   98816

// ---------------- device scratch (static: no allocation APIs) --------------
__device__ __align__(16) __half g_xh[BB * DD];
__device__ __align__(16) __half g_lh[LL * DD];
__device__ float g_x2[BB];
__device__ float g_l2[LL];

// ---------------- helpers ---------------------------------------------------
__device__ __forceinline__ uint32_t smem_u32(const void* p) {
    uint32_t a;
    asm("{ .reg .u64 t; cvta.to.shared.u64 t, %1; cvt.u32.u64 %0, t; }"
        : "=r"(a) : "l"(p));
    return a;
}

__device__ __forceinline__ float fast_ex2(float x) {
    float y;
    asm("ex2.approx.ftz.f32 %0, %1;" : "=f"(y) : "f"(x));
    return y;
}

#define CP_ASYNC_16(sa, ga)                                               \
    asm volatile("cp.async.cg.shared.global [%0], [%1], 16;" ::           \
                 "r"(sa), "l"(ga))
#define CP_COMMIT() asm volatile("cp.async.commit_group;" ::: "memory")
#define CP_WAIT0()  asm volatile("cp.async.wait_group 0;" ::: "memory")
#define CP_WAIT1()  asm volatile("cp.async.wait_group 1;" ::: "memory")

#define LDSM4(r0, r1, r2, r3, addr)                                        \
    asm volatile("ldmatrix.sync.aligned.m8n8.x4.shared.b16 {%0,%1,%2,%3}, [%4];" \
                 : "=r"(r0), "=r"(r1), "=r"(r2), "=r"(r3) : "r"(addr))

#define MMA16816(d, a0, a1, a2, a3, b0, b1)                                \
    asm volatile(                                                          \
        "mma.sync.aligned.m16n8k16.row.col.f32.f16.f16.f32 "               \
        "{%0,%1,%2,%3}, {%4,%5,%6,%7}, {%8,%9}, {%0,%1,%2,%3};"            \
        : "+f"((d)[0]), "+f"((d)[1]), "+f"((d)[2]), "+f"((d)[3])           \
        : "r"(a0), "r"(a1), "r"(a2), "r"(a3), "r"(b0), "r"(b1))

// ---------------- prep: fp32 -> fp16 + exact fp32 row norms ----------------
__global__ void __launch_bounds__(256) rbf_prep(const float* __restrict__ x,
                                                const float* __restrict__ lm) {
    int warp = threadIdx.x >> 5, lane = threadIdx.x & 31;
    int row = blockIdx.x * 8 + warp;
    const float* src;
    __half* dst;
    float* nrm;
    if (row < BB) {
        src = x + (size_t)row * DD;
        dst = g_xh + (size_t)row * DD;
        nrm = g_x2 + row;
    } else {
        int r = row - BB;
        if (r >= LL) return;
        src = lm + (size_t)r * DD;
        dst = g_lh + (size_t)r * DD;
        nrm = g_l2 + r;
    }
    float4 a = *(const float4*)(src + lane * 8);
    float4 b = *(const float4*)(src + lane * 8 + 4);
    float s = a.x * a.x + a.y * a.y + a.z * a.z + a.w * a.w +
              b.x * b.x + b.y * b.y + b.z * b.z + b.w * b.w;
    __half2 h0 = __floats2half2_rn(a.x, a.y);
    __half2 h1 = __floats2half2_rn(a.z, a.w);
    __half2 h2 = __floats2half2_rn(b.x, b.y);
    __half2 h3 = __floats2half2_rn(b.z, b.w);
    uint4 u;
    u.x = reinterpret_cast<uint32_t&>(h0);
    u.y = reinterpret_cast<uint32_t&>(h1);
    u.z = reinterpret_cast<uint32_t&>(h2);
    u.w = reinterpret_cast<uint32_t&>(h3);
    *reinterpret_cast<uint4*>(dst + lane * 8) = u;
#pragma unroll
    for (int o = 16; o; o >>= 1) s += __shfl_xor_sync(0xffffffffu, s, o);
    if (lane == 0) *nrm = s;
}

// ---------------- main GEMM + exp epilogue ----------------------------------
__global__ void __launch_bounds__(256, 2) rbf_main(float* __restrict__ out) {
    extern __shared__ char smem[];
    uint32_t sb = smem_u32(smem);
    int tid = threadIdx.x, wid = tid >> 5, lane = tid & 31;
    int m0 = blockIdx.y * TM;
    int n0 = blockIdx.x * TN;
    int wm = (wid & 3) * 32;   // warp M offset within tile
    int wn = (wid >> 2) * 64;  // warp N offset within tile

    // landmark norm tile -> smem
    if (tid < TN)
        reinterpret_cast<float*>(smem + SMEM_L2)[tid] = g_l2[n0 + tid];

    // ---- cp.async prefetch of one K-chunk (64 halves) into stage kc%3 ----
    auto prefetch = [&](int kc) {
        int stage = kc % 3;
        uint32_t sA = sb + stage * STAGE_BYTES;
        uint32_t sB = sA + 16384;
        int koff = kc * 64;
#pragma unroll
        for (int j = 0; j < 4; j++) {
            int idx = tid + j * 256;       // 0..1023
            int r = idx >> 3, c = idx & 7; // row, 16B-chunk
            uint32_t soff = (uint32_t)(r * 128 + ((c * 16) ^ ((r & 7) << 4)));
            const __half* ga = g_xh + (size_t)(m0 + r) * DD + koff + c * 8;
            const __half* gb = g_lh + (size_t)(n0 + r) * DD + koff + c * 8;
            CP_ASYNC_16(sA + soff, (unsigned long long)__cvta_generic_to_global((void*)ga));
            CP_ASYNC_16(sB + soff, (unsigned long long)__cvta_generic_to_global((void*)gb));
        }
        CP_COMMIT();
    };

    float acc[2][8][4];
#pragma unroll
    for (int mt = 0; mt < 2; mt++)
#pragma unroll
        for (int nt = 0; nt < 8; nt++)
#pragma unroll
            for (int i = 0; i < 4; i++) acc[mt][nt][i] = 0.0f;

    // lane-level smem addressing (constant across k-steps)
    int la = lane & 15;
    uint32_t xm = (uint32_t)((lane & 7) << 4);
    uint32_t kblA = (uint32_t)(((lane >> 4) & 1) << 4);  // k8 select for A
    int rb = (lane & 7) + (((lane >> 4) & 1) << 3);      // B row within 16
    uint32_t kblB = (uint32_t)(((lane >> 3) & 1) << 4);  // k8 select for B

    // prefetch depth 2
    prefetch(0);
    prefetch(1);

    // fragment double buffers (ks loop fully unrolled -> distinct registers)
    uint32_t af[2][8];     // [buf][a0:0-3, a1:4-7]
    uint32_t bf[2][8][2];  // [buf][nt][2]

#pragma unroll
    for (int kc = 0; kc < 4; kc++) {
        // stage kc must be complete; at kc<3 one newer group may stay in flight
        if (kc == 3) { CP_WAIT0(); } else { CP_WAIT1(); }
        __syncthreads();
        if (kc < 2) prefetch(kc + 2);

        int stage = kc % 3;
        uint32_t sA = sb + stage * STAGE_BYTES;
        uint32_t sB = sA + 16384;
        uint32_t aRow0 = sA + (uint32_t)((wm + la) * 128);
        uint32_t bRow = sB + (uint32_t)((wn + rb) * 128);

        // preload fragments for ks = 0 into buffer 0
        {
            uint32_t adA = kblA ^ xm;
            LDSM4(af[0][0], af[0][1], af[0][2], af[0][3], aRow0 + adA);
            LDSM4(af[0][4], af[0][5], af[0][6], af[0][7], aRow0 + 2048 + adA);
            uint32_t adB = kblB ^ xm;
#pragma unroll
            for (int ntp = 0; ntp < 4; ntp++) {
                uint32_t r0, r1, r2, r3;
                LDSM4(r0, r1, r2, r3, bRow + (uint32_t)(ntp * 2048) + adB);
                bf[0][2 * ntp][0] = r0; bf[0][2 * ntp][1] = r1;
                bf[0][2 * ntp + 1][0] = r2; bf[0][2 * ntp + 1][1] = r3;
            }
        }

#pragma unroll
        for (int ks = 0; ks < 4; ks++) {
            const int cur = ks & 1, nxt = cur ^ 1;
            if (ks < 3) {
                // issue next step's LDSMs first; MMAs below hide their latency
                uint32_t kb = (uint32_t)((ks + 1) * 32);
                uint32_t adB = (kb + kblB) ^ xm;
#pragma unroll
                for (int ntp = 0; ntp < 4; ntp++) {
                    uint32_t r0, r1, r2, r3;
                    LDSM4(r0, r1, r2, r3, bRow + (uint32_t)(ntp * 2048) + adB);
                    bf[nxt][2 * ntp][0] = r0; bf[nxt][2 * ntp][1] = r1;
                    bf[nxt][2 * ntp + 1][0] = r2; bf[nxt][2 * ntp + 1][1] = r3;
                }
                uint32_t adA = (kb + kblA) ^ xm;
                LDSM4(af[nxt][0], af[nxt][1], af[nxt][2], af[nxt][3],
                      aRow0 + adA);
                LDSM4(af[nxt][4], af[nxt][5], af[nxt][6], af[nxt][7],
                      aRow0 + 2048 + adA);
            }
#pragma unroll
            for (int nt = 0; nt < 8; nt++) {
                MMA16816(acc[0][nt], af[cur][0], af[cur][1], af[cur][2],
                         af[cur][3], bf[cur][nt][0], bf[cur][nt][1]);
                MMA16816(acc[1][nt], af[cur][4], af[cur][5], af[cur][6],
                         af[cur][7], bf[cur][nt][0], bf[cur][nt][1]);
            }
        }
        // no trailing barrier: next iteration's top barrier protects stage reuse
    }

    // ---- epilogue: ex2(C * max(x2 + l2 - 2*cross, 0)),  C = -log2(e)/256 ----
    const float* l2t = reinterpret_cast<const float*>(smem + SMEM_L2);
    const float C = -1.44269504088896f / 256.0f;
    int qr = lane >> 2, qc = (lane & 3) << 1;
#pragma unroll
    for (int mt = 0; mt < 2; mt++) {
#pragma unroll
        for (int h = 0; h < 2; h++) {
            int row = m0 + wm + mt * 16 + h * 8 + qr;
            float x2v = __ldg(&g_x2[row]);
            float* orow = out + (size_t)row * LL + n0 + wn;
#pragma unroll
            for (int nt = 0; nt < 8; nt++) {
                int col = nt * 8 + qc;
                float d0 = fmaxf(x2v + l2t[wn + col] -
                                 2.0f * acc[mt][nt][h * 2 + 0], 0.0f);
                float d1 = fmaxf(x2v + l2t[wn + col + 1] -
                                 2.0f * acc[mt][nt][h * 2 + 1], 0.0f);
                float2 o;
                o.x = fast_ex2(C * d0);
                o.y = fast_ex2(C * d1);
                *reinterpret_cast<float2*>(orow + col) = o;
            }
        }
    }
}

// ---------------- launch ----------------------------------------------------
extern "C" void kernel_launch(void* const* d_in, const int* in_sizes, int n_in,
                              void* d_out, int out_size) {
    const float* x = (const float*)d_in[0];   // [8192, 256]
    const float* lm = (const float*)d_in[1];  // [2048, 256]
    float* out = (float*)d_out;               // [8192, 2048]

    cudaFuncSetAttribute(rbf_main, cudaFuncAttributeMaxDynamicSharedMemorySize,
                         SMEM_SIZE);

    rbf_prep<<<(BB + LL) / 8, 256>>>(x, lm);
    dim3 grid(LL / TN, BB / TM);  // (16, 64)
    rbf_main<<<grid, 256, SMEM_SIZE>>>(out);
}